// round 1
// baseline (speedup 1.0000x reference)
#include <cuda_runtime.h>

#define B_DIM   512
#define E_DIM   8
#define IN_DIM  1024
#define OUT_DIM 1024

#define BM 64
#define BN 64
#define BK 16
#define ZSPLIT 4
#define E_PER_Z (E_DIM / ZSPLIT)

// Scratch for K-split partial sums (no cudaMalloc allowed).
__device__ float g_partial[ZSPLIT * B_DIM * OUT_DIM];

__global__ __launch_bounds__(256, 4)
void gemm_partial_kernel(const float* __restrict__ x,
                         const float* __restrict__ ew,
                         const float* __restrict__ W)
{
    // k-major smem tiles, padded to dodge the worst bank conflicts.
    __shared__ float As[BK][BM + 4];
    __shared__ float Bs[BK][BN + 4];

    const int bn  = blockIdx.x * BN;
    const int bm  = blockIdx.y * BM;
    const int z   = blockIdx.z;
    const int tid = threadIdx.x;

    // loader mapping: each thread loads one float4 (4 consecutive k) of one row
    const int lm = tid >> 2;        // 0..63 : row (m for A, n for B)
    const int lk = (tid & 3) * 4;   // 0,4,8,12 : k offset

    // compute mapping: 16x16 thread grid, 4x4 micro-tile
    const int tm = (tid >> 4) * 4;  // 0..60
    const int tn = (tid & 15) * 4;  // 0..60

    float acc[4][4];
    #pragma unroll
    for (int i = 0; i < 4; ++i)
        #pragma unroll
        for (int j = 0; j < 4; ++j)
            acc[i][j] = 0.0f;

    const float* xrow = x + (size_t)(bm + lm) * IN_DIM;

    #pragma unroll
    for (int ei = 0; ei < E_PER_Z; ++ei) {
        const int e = z * E_PER_Z + ei;
        const float scale = ew[(bm + lm) * E_DIM + e];  // fold expert weight into A
        const float* wrow = W + ((size_t)e * OUT_DIM + bn + lm) * IN_DIM;

        for (int k0 = 0; k0 < IN_DIM; k0 += BK) {
            float4 xa = *(const float4*)(xrow + k0 + lk);
            float4 wb = *(const float4*)(wrow + k0 + lk);
            xa.x *= scale; xa.y *= scale; xa.z *= scale; xa.w *= scale;

            __syncthreads();   // previous tile's compute done before overwrite
            As[lk + 0][lm] = xa.x;
            As[lk + 1][lm] = xa.y;
            As[lk + 2][lm] = xa.z;
            As[lk + 3][lm] = xa.w;
            Bs[lk + 0][lm] = wb.x;
            Bs[lk + 1][lm] = wb.y;
            Bs[lk + 2][lm] = wb.z;
            Bs[lk + 3][lm] = wb.w;
            __syncthreads();

            #pragma unroll
            for (int k = 0; k < BK; ++k) {
                const float4 av = *(const float4*)&As[k][tm];
                const float4 bv = *(const float4*)&Bs[k][tn];
                const float a0 = av.x, a1 = av.y, a2 = av.z, a3 = av.w;
                acc[0][0] = fmaf(a0, bv.x, acc[0][0]);
                acc[0][1] = fmaf(a0, bv.y, acc[0][1]);
                acc[0][2] = fmaf(a0, bv.z, acc[0][2]);
                acc[0][3] = fmaf(a0, bv.w, acc[0][3]);
                acc[1][0] = fmaf(a1, bv.x, acc[1][0]);
                acc[1][1] = fmaf(a1, bv.y, acc[1][1]);
                acc[1][2] = fmaf(a1, bv.z, acc[1][2]);
                acc[1][3] = fmaf(a1, bv.w, acc[1][3]);
                acc[2][0] = fmaf(a2, bv.x, acc[2][0]);
                acc[2][1] = fmaf(a2, bv.y, acc[2][1]);
                acc[2][2] = fmaf(a2, bv.z, acc[2][2]);
                acc[2][3] = fmaf(a2, bv.w, acc[2][3]);
                acc[3][0] = fmaf(a3, bv.x, acc[3][0]);
                acc[3][1] = fmaf(a3, bv.y, acc[3][1]);
                acc[3][2] = fmaf(a3, bv.z, acc[3][2]);
                acc[3][3] = fmaf(a3, bv.w, acc[3][3]);
            }
        }
    }

    float* outp = g_partial + ((size_t)z * B_DIM + bm + tm) * OUT_DIM + bn + tn;
    #pragma unroll
    for (int i = 0; i < 4; ++i) {
        float4 v = make_float4(acc[i][0], acc[i][1], acc[i][2], acc[i][3]);
        *(float4*)(outp + (size_t)i * OUT_DIM) = v;
    }
}

__global__ __launch_bounds__(256)
void combine_kernel(const float* __restrict__ ew,
                    const float* __restrict__ bias,
                    float* __restrict__ out)
{
    const int idx = blockIdx.x * blockDim.x + threadIdx.x; // 0 .. B*OUT/4-1
    const int b   = idx >> 8;                // / (OUT_DIM/4)
    const int o   = (idx & 255) * 4;
    const size_t off = (size_t)b * OUT_DIM + o;

    const size_t plane = (size_t)B_DIM * OUT_DIM;
    float4 s = *(const float4*)&g_partial[off];
    #pragma unroll
    for (int zz = 1; zz < ZSPLIT; ++zz) {
        float4 p = *(const float4*)&g_partial[zz * plane + off];
        s.x += p.x; s.y += p.y; s.z += p.z; s.w += p.w;
    }

    #pragma unroll
    for (int e = 0; e < E_DIM; ++e) {
        const float w = ew[b * E_DIM + e];
        const float4 bv = *(const float4*)&bias[e * OUT_DIM + o];
        s.x = fmaf(w, bv.x, s.x);
        s.y = fmaf(w, bv.y, s.y);
        s.z = fmaf(w, bv.z, s.z);
        s.w = fmaf(w, bv.w, s.w);
    }
    *(float4*)(out + off) = s;
}

extern "C" void kernel_launch(void* const* d_in, const int* in_sizes, int n_in,
                              void* d_out, int out_size)
{
    const float* x    = (const float*)d_in[0];   // [512, 1024]
    const float* ew   = (const float*)d_in[1];   // [512, 8]
    const float* W    = (const float*)d_in[2];   // [8, 1024, 1024] (E, OUT, IN)
    const float* bias = (const float*)d_in[3];   // [8, 1024]
    float* out = (float*)d_out;                  // [512, 1024]

    dim3 grid(OUT_DIM / BN, B_DIM / BM, ZSPLIT); // (16, 8, 4) = 512 blocks
    gemm_partial_kernel<<<grid, 256>>>(x, ew, W);

    const int total4 = B_DIM * OUT_DIM / 4;      // 131072
    combine_kernel<<<total4 / 256, 256>>>(ew, bias, out);
}

// round 4
// speedup vs baseline: 2.6422x; 2.6422x over previous
#include <cuda_runtime.h>
#include <cstdint>

#define B_DIM   512
#define E_DIM   8
#define IN_DIM  1024
#define OUT_DIM 1024

#define MT 128
#define NT 128
#define KC 32                       // K chunk (bf16 elems)
#define ZSPLIT 4
#define E_PER_Z (E_DIM / ZSPLIT)    // 2
#define KPZ (E_PER_Z * IN_DIM)      // 2048
#define NCHUNK (KPZ / KC)           // 64
#define THREADS 256

__device__ float g_partial[ZSPLIT * B_DIM * OUT_DIM];

// ---------- helpers ----------
__device__ __forceinline__ uint32_t smem_u32(const void* p) {
    uint32_t a;
    asm("{ .reg .u64 t; cvta.to.shared.u64 t, %1; cvt.u32.u64 %0, t; }" : "=r"(a) : "l"(p));
    return a;
}
// pack {low half = v0, high half = v1}
__device__ __forceinline__ uint32_t pack2(float v0, float v1) {
    uint32_t r;
    asm("cvt.rn.bf16x2.f32 %0, %1, %2;" : "=r"(r) : "f"(v1), "f"(v0));
    return r;
}
__device__ __forceinline__ void ldsm_x4(uint32_t* r, uint32_t addr) {
    asm volatile("ldmatrix.sync.aligned.m8n8.x4.shared.b16 {%0,%1,%2,%3}, [%4];"
                 : "=r"(r[0]), "=r"(r[1]), "=r"(r[2]), "=r"(r[3]) : "r"(addr));
}
__device__ __forceinline__ void mma_bf16(float* c, const uint32_t* a,
                                         uint32_t b0, uint32_t b1) {
    asm volatile(
        "mma.sync.aligned.m16n8k16.row.col.f32.bf16.bf16.f32 "
        "{%0,%1,%2,%3}, {%4,%5,%6,%7}, {%8,%9}, {%0,%1,%2,%3};"
        : "+f"(c[0]), "+f"(c[1]), "+f"(c[2]), "+f"(c[3])
        : "r"(a[0]), "r"(a[1]), "r"(a[2]), "r"(a[3]), "r"(b0), "r"(b1));
}
// split 8 scaled floats into hi/lo bf16 uint4s
__device__ __forceinline__ void split8(float4 v0, float4 v1, float s,
                                       uint4& h, uint4& l) {
    float f0 = v0.x * s, f1 = v0.y * s, f2 = v0.z * s, f3 = v0.w * s;
    float f4 = v1.x * s, f5 = v1.y * s, f6 = v1.z * s, f7 = v1.w * s;
    h.x = pack2(f0, f1); h.y = pack2(f2, f3);
    h.z = pack2(f4, f5); h.w = pack2(f6, f7);
    l.x = pack2(f0 - __uint_as_float(h.x << 16), f1 - __uint_as_float(h.x & 0xffff0000u));
    l.y = pack2(f2 - __uint_as_float(h.y << 16), f3 - __uint_as_float(h.y & 0xffff0000u));
    l.z = pack2(f4 - __uint_as_float(h.z << 16), f5 - __uint_as_float(h.z & 0xffff0000u));
    l.w = pack2(f6 - __uint_as_float(h.w << 16), f7 - __uint_as_float(h.w & 0xffff0000u));
}
// smem byte offset for (row, 16B-chunk kb) with XOR swizzle on row[2:1]
__device__ __forceinline__ uint32_t sw_off(int r, int kb) {
    return (uint32_t)(r * 64 + ((kb ^ ((r >> 1) & 3)) << 4));
}

// ---------- GEMM ----------
__global__ __launch_bounds__(THREADS, 1)
void moe_gemm_kernel(const float* __restrict__ x,
                     const float* __restrict__ ew,
                     const float* __restrict__ W)
{
    __shared__ __align__(16) uint8_t sAh[128 * 64];
    __shared__ __align__(16) uint8_t sAl[128 * 64];
    __shared__ __align__(16) uint8_t sBh[128 * 64];
    __shared__ __align__(16) uint8_t sBl[128 * 64];

    const int tid  = threadIdx.x;
    const int lane = tid & 31;
    const int wid  = tid >> 5;
    const int bn = blockIdx.x * NT;
    const int bm = blockIdx.y * MT;
    const int z  = blockIdx.z;

    const int lr = tid >> 1;        // loader row 0..127
    const int lh = tid & 1;         // k-half (16 elems)
    const int wm = wid >> 2;        // warp m (0..1) -> 64 rows
    const int wn = wid & 3;         // warp n (0..3) -> 32 cols

    const uint32_t uAh = smem_u32(sAh), uAl = smem_u32(sAl);
    const uint32_t uBh = smem_u32(sBh), uBl = smem_u32(sBl);

    float acc[16][4];
    #pragma unroll
    for (int i = 0; i < 16; ++i)
        #pragma unroll
        for (int j = 0; j < 4; ++j) acc[i][j] = 0.0f;

    float4 ra[4], rb[4];
    // prefetch chunk 0
    {
        const int e = z * E_PER_Z;
        const float* ap = x + (size_t)(bm + lr) * IN_DIM + lh * 16;
        const float* bp = W + ((size_t)e * OUT_DIM + bn + lr) * IN_DIM + lh * 16;
        #pragma unroll
        for (int j = 0; j < 4; ++j) { ra[j] = __ldg((const float4*)(ap + 4 * j)); }
        #pragma unroll
        for (int j = 0; j < 4; ++j) { rb[j] = __ldg((const float4*)(bp + 4 * j)); }
    }

    for (int c = 0; c < NCHUNK; ++c) {
        const int e = z * E_PER_Z + (c >> 5);

        // convert + STS (this chunk)
        {
            const float s = __ldg(&ew[(size_t)(bm + lr) * E_DIM + e]);
            uint4 h0, l0, h1, l1;
            split8(ra[0], ra[1], s, h0, l0);
            split8(ra[2], ra[3], s, h1, l1);
            const int kb = lh * 2;
            *(uint4*)(sAh + sw_off(lr, kb))     = h0;
            *(uint4*)(sAh + sw_off(lr, kb + 1)) = h1;
            *(uint4*)(sAl + sw_off(lr, kb))     = l0;
            *(uint4*)(sAl + sw_off(lr, kb + 1)) = l1;
            split8(rb[0], rb[1], 1.0f, h0, l0);
            split8(rb[2], rb[3], 1.0f, h1, l1);
            *(uint4*)(sBh + sw_off(lr, kb))     = h0;
            *(uint4*)(sBh + sw_off(lr, kb + 1)) = h1;
            *(uint4*)(sBl + sw_off(lr, kb))     = l0;
            *(uint4*)(sBl + sw_off(lr, kb + 1)) = l1;
        }
        __syncthreads();

        // prefetch next chunk (overlaps with MMA below)
        if (c + 1 < NCHUNK) {
            const int cn = c + 1;
            const int en = z * E_PER_Z + (cn >> 5);
            const int i0 = (cn & 31) * KC + lh * 16;
            const float* ap = x + (size_t)(bm + lr) * IN_DIM + i0;
            const float* bp = W + ((size_t)en * OUT_DIM + bn + lr) * IN_DIM + i0;
            #pragma unroll
            for (int j = 0; j < 4; ++j) { ra[j] = __ldg((const float4*)(ap + 4 * j)); }
            #pragma unroll
            for (int j = 0; j < 4; ++j) { rb[j] = __ldg((const float4*)(bp + 4 * j)); }
        }

        // compute: 2 k-steps of 16
        #pragma unroll
        for (int ks = 0; ks < 2; ++ks) {
            uint32_t ahi[4][4], alo[4][4];
            const int ar = (lane & 15);
            const int akb = ks * 2 + (lane >> 4);
            #pragma unroll
            for (int mt = 0; mt < 4; ++mt) {
                const int r = wm * 64 + mt * 16 + ar;
                const uint32_t off = sw_off(r, akb);
                ldsm_x4(ahi[mt], uAh + off);
                ldsm_x4(alo[mt], uAl + off);
            }
            uint32_t bhi[2][4], blo[2][4];
            #pragma unroll
            for (int p = 0; p < 2; ++p) {
                const int r = wn * 32 + p * 16 + (lane & 7) + ((lane >> 4) & 1) * 8;
                const int kb = ks * 2 + ((lane >> 3) & 1);
                const uint32_t off = sw_off(r, kb);
                ldsm_x4(bhi[p], uBh + off);
                ldsm_x4(blo[p], uBl + off);
            }
            #pragma unroll
            for (int mt = 0; mt < 4; ++mt)
                #pragma unroll
                for (int p = 0; p < 2; ++p)
                    #pragma unroll
                    for (int sub = 0; sub < 2; ++sub) {
                        float* cacc = acc[mt * 4 + p * 2 + sub];
                        const uint32_t b0h = bhi[p][sub * 2], b1h = bhi[p][sub * 2 + 1];
                        mma_bf16(cacc, ahi[mt], b0h, b1h);
                        mma_bf16(cacc, ahi[mt], blo[p][sub * 2], blo[p][sub * 2 + 1]);
                        mma_bf16(cacc, alo[mt], b0h, b1h);
                    }
        }
        __syncthreads();
    }

    // epilogue -> g_partial
    const int tr = lane >> 2;            // 0..7
    const int tc = (lane & 3) * 2;
    #pragma unroll
    for (int mt = 0; mt < 4; ++mt) {
        const int row = bm + wm * 64 + mt * 16 + tr;
        float* base = g_partial + ((size_t)z * B_DIM + row) * OUT_DIM + bn + wn * 32;
        #pragma unroll
        for (int nt = 0; nt < 4; ++nt) {
            const float* a4 = acc[mt * 4 + nt];
            *(float2*)(base + nt * 8 + tc)                      = make_float2(a4[0], a4[1]);
            *(float2*)(base + 8 * (size_t)OUT_DIM + nt * 8 + tc) = make_float2(a4[2], a4[3]);
        }
    }
}

// ---------- combine ----------
__global__ __launch_bounds__(256)
void combine_kernel(const float* __restrict__ ew,
                    const float* __restrict__ bias,
                    float* __restrict__ out)
{
    const int idx = blockIdx.x * blockDim.x + threadIdx.x;
    const int b   = idx >> 8;
    const int o   = (idx & 255) * 4;
    const size_t off = (size_t)b * OUT_DIM + o;

    const size_t plane = (size_t)B_DIM * OUT_DIM;
    float4 s = *(const float4*)&g_partial[off];
    #pragma unroll
    for (int zz = 1; zz < ZSPLIT; ++zz) {
        float4 p = *(const float4*)&g_partial[zz * plane + off];
        s.x += p.x; s.y += p.y; s.z += p.z; s.w += p.w;
    }
    #pragma unroll
    for (int e = 0; e < E_DIM; ++e) {
        const float w = ew[b * E_DIM + e];
        const float4 bv = *(const float4*)&bias[e * OUT_DIM + o];
        s.x = fmaf(w, bv.x, s.x);
        s.y = fmaf(w, bv.y, s.y);
        s.z = fmaf(w, bv.z, s.z);
        s.w = fmaf(w, bv.w, s.w);
    }
    *(float4*)(out + off) = s;
}

extern "C" void kernel_launch(void* const* d_in, const int* in_sizes, int n_in,
                              void* d_out, int out_size)
{
    const float* x    = (const float*)d_in[0];   // [512, 1024]
    const float* ew   = (const float*)d_in[1];   // [512, 8]
    const float* W    = (const float*)d_in[2];   // [8, 1024, 1024]
    const float* bias = (const float*)d_in[3];   // [8, 1024]
    float* out = (float*)d_out;

    dim3 grid(OUT_DIM / NT, B_DIM / MT, ZSPLIT); // (8, 4, 4) = 128 CTAs
    moe_gemm_kernel<<<grid, THREADS>>>(x, ew, W);

    const int total4 = B_DIM * OUT_DIM / 4;
    combine_kernel<<<total4 / 256, 256>>>(ew, bias, out);
}

// round 5
// speedup vs baseline: 4.5757x; 1.7318x over previous
#include <cuda_runtime.h>
#include <cuda_fp16.h>
#include <cstdint>

#define B_DIM   512
#define E_DIM   8
#define IN_DIM  1024
#define OUT_DIM 1024

#define MT 128
#define NT 128
#define KC 64                        // K chunk (fp16 elems) = 128B row
#define NCHUNK (IN_DIM / KC)         // 16
#define THREADS 256

#define BUFSZ   (48 * 1024)          // xh(16K) + xl(16K) + wh(16K)
#define A_OFF   0
#define AL_OFF  16384
#define B_OFF   32768
#define SMEM_TOTAL (2 * BUFSZ)       // 96 KB double-buffered

// per-launch scratch (no cudaMalloc allowed)
__device__ __half g_xh[B_DIM * IN_DIM];
__device__ __half g_xl[B_DIM * IN_DIM];
__device__ __half g_wh[E_DIM * OUT_DIM * IN_DIM];
__device__ float  g_plane[E_DIM * B_DIM * OUT_DIM];

// ---------- helpers ----------
__device__ __forceinline__ uint32_t smem_u32(const void* p) {
    uint32_t a;
    asm("{ .reg .u64 t; cvta.to.shared.u64 t, %1; cvt.u32.u64 %0, t; }" : "=r"(a) : "l"(p));
    return a;
}
__device__ __forceinline__ void cp16(uint32_t dst, const void* src) {
    asm volatile("cp.async.cg.shared.global [%0], [%1], 16;" :: "r"(dst), "l"(src));
}
__device__ __forceinline__ void ldsm_x4(uint32_t* r, uint32_t addr) {
    asm volatile("ldmatrix.sync.aligned.m8n8.x4.shared.b16 {%0,%1,%2,%3}, [%4];"
                 : "=r"(r[0]), "=r"(r[1]), "=r"(r[2]), "=r"(r[3]) : "r"(addr));
}
__device__ __forceinline__ void mma_fp16(float* c, const uint32_t* a,
                                         uint32_t b0, uint32_t b1) {
    asm volatile(
        "mma.sync.aligned.m16n8k16.row.col.f32.f16.f16.f32 "
        "{%0,%1,%2,%3}, {%4,%5,%6,%7}, {%8,%9}, {%0,%1,%2,%3};"
        : "+f"(c[0]), "+f"(c[1]), "+f"(c[2]), "+f"(c[3])
        : "r"(a[0]), "r"(a[1]), "r"(a[2]), "r"(a[3]), "r"(b0), "r"(b1));
}
// swizzled byte offset inside a 128x(64 halves = 128B) tile
__device__ __forceinline__ uint32_t sw_off(int r, int kb) {
    return (uint32_t)(r * 128 + ((kb ^ (r & 7)) << 4));
}

// ---------- prep: split x into fp16 hi/lo ----------
__global__ __launch_bounds__(256)
void prep_x_kernel(const float* __restrict__ x)
{
    const int idx = (blockIdx.x * 256 + threadIdx.x) * 4;
    float4 v = *(const float4*)(x + idx);
    __half h0 = __float2half_rn(v.x), h1 = __float2half_rn(v.y);
    __half h2 = __float2half_rn(v.z), h3 = __float2half_rn(v.w);
    __half l0 = __float2half_rn(v.x - __half2float(h0));
    __half l1 = __float2half_rn(v.y - __half2float(h1));
    __half l2 = __float2half_rn(v.z - __half2float(h2));
    __half l3 = __float2half_rn(v.w - __half2float(h3));
    *(uint2*)(g_xh + idx) = *(uint2*)&(__half2[2]){{h0, h1}, {h2, h3}};
    *(uint2*)(g_xl + idx) = *(uint2*)&(__half2[2]){{l0, l1}, {l2, l3}};
}

// ---------- prep: W -> fp16 ----------
__global__ __launch_bounds__(256)
void prep_w_kernel(const float* __restrict__ W)
{
    const size_t idx = ((size_t)blockIdx.x * 256 + threadIdx.x) * 4;
    float4 v = *(const float4*)(W + idx);
    __half2 a = __floats2half2_rn(v.x, v.y);
    __half2 b = __floats2half2_rn(v.z, v.w);
    *(uint2*)(g_wh + idx) = make_uint2(*(uint32_t*)&a, *(uint32_t*)&b);
}

// ---------- GEMM: plane_e = x @ W_e^T ----------
__global__ __launch_bounds__(THREADS, 1)
void moe_gemm_kernel()
{
    extern __shared__ __align__(16) uint8_t smem[];
    const uint32_t sbase = smem_u32(smem);

    const int tid  = threadIdx.x;
    const int lane = tid & 31;
    const int wid  = tid >> 5;
    const int bn = blockIdx.x * NT;
    const int bm = blockIdx.y * MT;
    const int e  = blockIdx.z;

    const int wm = wid >> 2;        // 0..1 -> 64 rows
    const int wn = wid & 3;         // 0..3 -> 32 cols

    const __half* wp = g_wh + (size_t)e * OUT_DIM * IN_DIM;

    float acc[16][4];
    #pragma unroll
    for (int i = 0; i < 16; ++i)
        #pragma unroll
        for (int j = 0; j < 4; ++j) acc[i][j] = 0.0f;

    // issue all cp.asyncs for chunk c into buffer buf
    auto issue = [&](int c, int buf) {
        const int i0 = c * KC;
        const uint32_t base = sbase + buf * BUFSZ;
        #pragma unroll
        for (int j = 0; j < 4; ++j) {
            const int cid = tid + j * 256;     // 0..1023
            const int row = cid >> 3;
            const int kb  = cid & 7;
            const uint32_t d = sw_off(row, kb);
            const int goff = i0 + kb * 8;
            cp16(base + A_OFF  + d, g_xh + (size_t)(bm + row) * IN_DIM + goff);
            cp16(base + AL_OFF + d, g_xl + (size_t)(bm + row) * IN_DIM + goff);
            cp16(base + B_OFF  + d, wp   + (size_t)(bn + row) * IN_DIM + goff);
        }
        asm volatile("cp.async.commit_group;" ::: "memory");
    };

    issue(0, 0);

    for (int c = 0; c < NCHUNK; ++c) {
        const int buf = c & 1;
        if (c + 1 < NCHUNK) {
            issue(c + 1, buf ^ 1);
            asm volatile("cp.async.wait_group 1;" ::: "memory");
        } else {
            asm volatile("cp.async.wait_group 0;" ::: "memory");
        }
        __syncthreads();

        const uint32_t uA  = sbase + buf * BUFSZ + A_OFF;
        const uint32_t uAl = sbase + buf * BUFSZ + AL_OFF;
        const uint32_t uB  = sbase + buf * BUFSZ + B_OFF;

        #pragma unroll
        for (int ks = 0; ks < 4; ++ks) {
            uint32_t ah[4][4], al[4][4];
            const int ar  = lane & 15;
            const int akb = ks * 2 + (lane >> 4);
            #pragma unroll
            for (int mt = 0; mt < 4; ++mt) {
                const int r = wm * 64 + mt * 16 + ar;
                const uint32_t off = sw_off(r, akb);
                ldsm_x4(ah[mt], uA + off);
                ldsm_x4(al[mt], uAl + off);
            }
            uint32_t bh[2][4];
            #pragma unroll
            for (int p = 0; p < 2; ++p) {
                const int r  = wn * 32 + p * 16 + (lane & 7) + ((lane >> 4) & 1) * 8;
                const int kb = ks * 2 + ((lane >> 3) & 1);
                ldsm_x4(bh[p], uB + sw_off(r, kb));
            }
            #pragma unroll
            for (int mt = 0; mt < 4; ++mt)
                #pragma unroll
                for (int p = 0; p < 2; ++p)
                    #pragma unroll
                    for (int sub = 0; sub < 2; ++sub) {
                        float* cacc = acc[mt * 4 + p * 2 + sub];
                        const uint32_t b0 = bh[p][sub * 2], b1 = bh[p][sub * 2 + 1];
                        mma_fp16(cacc, ah[mt], b0, b1);
                        mma_fp16(cacc, al[mt], b0, b1);
                    }
        }
        __syncthreads();
    }

    // epilogue -> per-expert plane
    const int tr = lane >> 2;
    const int tc = (lane & 3) * 2;
    #pragma unroll
    for (int mt = 0; mt < 4; ++mt) {
        const int row = bm + wm * 64 + mt * 16 + tr;
        float* base = g_plane + ((size_t)e * B_DIM + row) * OUT_DIM + bn + wn * 32;
        #pragma unroll
        for (int nt = 0; nt < 4; ++nt) {
            const float* a4 = acc[mt * 4 + nt];
            *(float2*)(base + nt * 8 + tc)                       = make_float2(a4[0], a4[1]);
            *(float2*)(base + 8 * (size_t)OUT_DIM + nt * 8 + tc) = make_float2(a4[2], a4[3]);
        }
    }
}

// ---------- combine: blend 8 planes with ew, add blended bias ----------
__global__ __launch_bounds__(256)
void combine_kernel(const float* __restrict__ ew,
                    const float* __restrict__ bias,
                    float* __restrict__ out)
{
    const int idx = blockIdx.x * blockDim.x + threadIdx.x;
    const int b   = idx >> 8;
    const int o   = (idx & 255) * 4;
    const size_t off = (size_t)b * OUT_DIM + o;
    const size_t plane = (size_t)B_DIM * OUT_DIM;

    float w[E_DIM];
    #pragma unroll
    for (int e = 0; e < E_DIM; ++e) w[e] = ew[b * E_DIM + e];

    float4 s = make_float4(0.f, 0.f, 0.f, 0.f);
    #pragma unroll
    for (int e = 0; e < E_DIM; ++e) {
        const float4 p = *(const float4*)&g_plane[e * plane + off];
        s.x = fmaf(w[e], p.x, s.x);
        s.y = fmaf(w[e], p.y, s.y);
        s.z = fmaf(w[e], p.z, s.z);
        s.w = fmaf(w[e], p.w, s.w);
    }
    #pragma unroll
    for (int e = 0; e < E_DIM; ++e) {
        const float4 bv = *(const float4*)&bias[e * OUT_DIM + o];
        s.x = fmaf(w[e], bv.x, s.x);
        s.y = fmaf(w[e], bv.y, s.y);
        s.z = fmaf(w[e], bv.z, s.z);
        s.w = fmaf(w[e], bv.w, s.w);
    }
    *(float4*)(out + off) = s;
}

extern "C" void kernel_launch(void* const* d_in, const int* in_sizes, int n_in,
                              void* d_out, int out_size)
{
    const float* x    = (const float*)d_in[0];   // [512, 1024]
    const float* ew   = (const float*)d_in[1];   // [512, 8]
    const float* W    = (const float*)d_in[2];   // [8, 1024, 1024]
    const float* bias = (const float*)d_in[3];   // [8, 1024]
    float* out = (float*)d_out;

    prep_x_kernel<<<B_DIM * IN_DIM / 4 / 256, 256>>>(x);
    prep_w_kernel<<<E_DIM * OUT_DIM * IN_DIM / 4 / 256, 256>>>(W);

    cudaFuncSetAttribute(moe_gemm_kernel,
                         cudaFuncAttributeMaxDynamicSharedMemorySize, SMEM_TOTAL);
    dim3 grid(OUT_DIM / NT, B_DIM / MT, E_DIM);   // (8, 4, 8) = 256 CTAs
    moe_gemm_kernel<<<grid, THREADS, SMEM_TOTAL>>>();

    combine_kernel<<<B_DIM * OUT_DIM / 4 / 256, 256>>>(ew, bias, out);
}

// round 6
// speedup vs baseline: 6.4206x; 1.4032x over previous
#include <cuda_runtime.h>
#include <cuda_fp16.h>
#include <cstdint>

#define B_DIM   512
#define E_DIM   8
#define IN_DIM  1024
#define OUT_DIM 1024

#define MT 128
#define NT 128
#define KC 64                        // K chunk (fp16) = 128B row
#define ZSPLIT 4
#define E_PER_Z 2
#define NCHUNK (E_PER_Z * IN_DIM / KC)   // 32
#define THREADS 256

#define TILE_BYTES (128 * 128)       // 16KB per operand tile
#define BUFSZ (2 * TILE_BYTES)       // A + B
#define SMEM_TOTAL (2 * BUFSZ)       // 64KB double-buffered

// scratch (no cudaMalloc allowed)
__device__ __half g_xs[E_DIM * B_DIM * IN_DIM];      // pre-blended A planes, 8MB
__device__ __half g_wh[E_DIM * OUT_DIM * IN_DIM];    // fp16 W, 16.8MB
__device__ float  g_partial[ZSPLIT * B_DIM * OUT_DIM];

// ---------- helpers ----------
__device__ __forceinline__ uint32_t smem_u32(const void* p) {
    uint32_t a;
    asm("{ .reg .u64 t; cvta.to.shared.u64 t, %1; cvt.u32.u64 %0, t; }" : "=r"(a) : "l"(p));
    return a;
}
__device__ __forceinline__ void cp16(uint32_t dst, const void* src) {
    asm volatile("cp.async.cg.shared.global [%0], [%1], 16;" :: "r"(dst), "l"(src));
}
__device__ __forceinline__ void ldsm_x4(uint32_t* r, uint32_t addr) {
    asm volatile("ldmatrix.sync.aligned.m8n8.x4.shared.b16 {%0,%1,%2,%3}, [%4];"
                 : "=r"(r[0]), "=r"(r[1]), "=r"(r[2]), "=r"(r[3]) : "r"(addr));
}
__device__ __forceinline__ void mma_fp16(float* c, const uint32_t* a,
                                         uint32_t b0, uint32_t b1) {
    asm volatile(
        "mma.sync.aligned.m16n8k16.row.col.f32.f16.f16.f32 "
        "{%0,%1,%2,%3}, {%4,%5,%6,%7}, {%8,%9}, {%0,%1,%2,%3};"
        : "+f"(c[0]), "+f"(c[1]), "+f"(c[2]), "+f"(c[3])
        : "r"(a[0]), "r"(a[1]), "r"(a[2]), "r"(a[3]), "r"(b0), "r"(b1));
}
__device__ __forceinline__ uint32_t sw_off(int r, int kb) {
    return (uint32_t)(r * 128 + ((kb ^ (r & 7)) << 4));
}

// ---------- prep: W->fp16 and x->pre-blended fp16 planes ----------
#define W_BLOCKS (E_DIM * OUT_DIM * IN_DIM / 4 / 256)   // 8192
#define X_BLOCKS (B_DIM * IN_DIM / 4 / 256)             // 512
__global__ __launch_bounds__(256)
void prep_kernel(const float* __restrict__ x,
                 const float* __restrict__ ew,
                 const float* __restrict__ W)
{
    if (blockIdx.x < W_BLOCKS) {
        const size_t idx = ((size_t)blockIdx.x * 256 + threadIdx.x) * 4;
        float4 v = *(const float4*)(W + idx);
        __half2 a = __floats2half2_rn(v.x, v.y);
        __half2 b = __floats2half2_rn(v.z, v.w);
        *(uint2*)(g_wh + idx) = make_uint2(*(uint32_t*)&a, *(uint32_t*)&b);
    } else {
        const int idx = ((blockIdx.x - W_BLOCKS) * 256 + threadIdx.x) * 4;
        const int b = idx >> 10;
        float4 v = *(const float4*)(x + idx);
        #pragma unroll
        for (int e = 0; e < E_DIM; ++e) {
            const float s = __ldg(&ew[b * E_DIM + e]);
            __half2 a = __floats2half2_rn(v.x * s, v.y * s);
            __half2 c = __floats2half2_rn(v.z * s, v.w * s);
            *(uint2*)(g_xs + (size_t)e * (B_DIM * IN_DIM) + idx) =
                make_uint2(*(uint32_t*)&a, *(uint32_t*)&c);
        }
    }
}

// ---------- GEMM: partial_z = sum_{e in z} (ew_e*x) @ W_e^T ----------
__global__ __launch_bounds__(THREADS, 1)
void moe_gemm_kernel()
{
    extern __shared__ __align__(16) uint8_t smem[];
    const uint32_t sbase = smem_u32(smem);

    const int tid  = threadIdx.x;
    const int lane = tid & 31;
    const int wid  = tid >> 5;
    const int bn = blockIdx.x * NT;
    const int bm = blockIdx.y * MT;
    const int z  = blockIdx.z;

    const int wm = wid >> 2;        // 0..1 -> 64 rows
    const int wn = wid & 3;         // 0..3 -> 32 cols

    float acc[16][4];
    #pragma unroll
    for (int i = 0; i < 16; ++i)
        #pragma unroll
        for (int j = 0; j < 4; ++j) acc[i][j] = 0.0f;

    auto issue = [&](int c, int buf) {
        const int e  = z * E_PER_Z + (c >> 4);
        const int k0 = (c & 15) * KC;
        const __half* ap = g_xs + (size_t)e * (B_DIM * IN_DIM);
        const __half* bp = g_wh + (size_t)e * (OUT_DIM * IN_DIM);
        const uint32_t base = sbase + buf * BUFSZ;
        #pragma unroll
        for (int j = 0; j < 4; ++j) {
            const int cid = tid + j * 256;     // 0..1023
            const int row = cid >> 3;
            const int kb  = cid & 7;
            const uint32_t d = sw_off(row, kb);
            const int goff = k0 + kb * 8;
            cp16(base + d,              ap + (size_t)(bm + row) * IN_DIM + goff);
            cp16(base + TILE_BYTES + d, bp + (size_t)(bn + row) * IN_DIM + goff);
        }
        asm volatile("cp.async.commit_group;" ::: "memory");
    };

    issue(0, 0);

    for (int c = 0; c < NCHUNK; ++c) {
        const int buf = c & 1;
        if (c + 1 < NCHUNK) {
            issue(c + 1, buf ^ 1);
            asm volatile("cp.async.wait_group 1;" ::: "memory");
        } else {
            asm volatile("cp.async.wait_group 0;" ::: "memory");
        }
        __syncthreads();

        const uint32_t uA = sbase + buf * BUFSZ;
        const uint32_t uB = uA + TILE_BYTES;

        #pragma unroll
        for (int ks = 0; ks < 4; ++ks) {
            uint32_t ah[4][4];
            const int ar  = lane & 15;
            const int akb = ks * 2 + (lane >> 4);
            #pragma unroll
            for (int mt = 0; mt < 4; ++mt) {
                const int r = wm * 64 + mt * 16 + ar;
                ldsm_x4(ah[mt], uA + sw_off(r, akb));
            }
            uint32_t bh[2][4];
            #pragma unroll
            for (int p = 0; p < 2; ++p) {
                const int r  = wn * 32 + p * 16 + (lane & 7) + ((lane >> 4) & 1) * 8;
                const int kb = ks * 2 + ((lane >> 3) & 1);
                ldsm_x4(bh[p], uB + sw_off(r, kb));
            }
            #pragma unroll
            for (int mt = 0; mt < 4; ++mt)
                #pragma unroll
                for (int p = 0; p < 2; ++p)
                    #pragma unroll
                    for (int sub = 0; sub < 2; ++sub)
                        mma_fp16(acc[mt * 4 + p * 2 + sub], ah[mt],
                                 bh[p][sub * 2], bh[p][sub * 2 + 1]);
        }
        __syncthreads();
    }

    // epilogue -> partial plane z
    const int tr = lane >> 2;
    const int tc = (lane & 3) * 2;
    #pragma unroll
    for (int mt = 0; mt < 4; ++mt) {
        const int row = bm + wm * 64 + mt * 16 + tr;
        float* base = g_partial + ((size_t)z * B_DIM + row) * OUT_DIM + bn + wn * 32;
        #pragma unroll
        for (int nt = 0; nt < 4; ++nt) {
            const float* a4 = acc[mt * 4 + nt];
            *(float2*)(base + nt * 8 + tc)                       = make_float2(a4[0], a4[1]);
            *(float2*)(base + 8 * (size_t)OUT_DIM + nt * 8 + tc) = make_float2(a4[2], a4[3]);
        }
    }
}

// ---------- combine: sum 4 partials + blended bias ----------
__global__ __launch_bounds__(256)
void combine_kernel(const float* __restrict__ ew,
                    const float* __restrict__ bias,
                    float* __restrict__ out)
{
    const int idx = (blockIdx.x * 256 + threadIdx.x) * 8;   // 8 floats/thread
    const int b   = idx >> 10;
    const int o   = idx & 1023;
    const size_t off = (size_t)b * OUT_DIM + o;
    const size_t plane = (size_t)B_DIM * OUT_DIM;

    float w[E_DIM];
    #pragma unroll
    for (int e = 0; e < E_DIM; ++e) w[e] = __ldg(&ew[b * E_DIM + e]);

    float4 s0 = make_float4(0.f, 0.f, 0.f, 0.f);
    float4 s1 = make_float4(0.f, 0.f, 0.f, 0.f);
    #pragma unroll
    for (int zz = 0; zz < ZSPLIT; ++zz) {
        const float4 p0 = *(const float4*)&g_partial[zz * plane + off];
        const float4 p1 = *(const float4*)&g_partial[zz * plane + off + 4];
        s0.x += p0.x; s0.y += p0.y; s0.z += p0.z; s0.w += p0.w;
        s1.x += p1.x; s1.y += p1.y; s1.z += p1.z; s1.w += p1.w;
    }
    #pragma unroll
    for (int e = 0; e < E_DIM; ++e) {
        const float4 b0 = *(const float4*)&bias[e * OUT_DIM + o];
        const float4 b1 = *(const float4*)&bias[e * OUT_DIM + o + 4];
        s0.x = fmaf(w[e], b0.x, s0.x); s0.y = fmaf(w[e], b0.y, s0.y);
        s0.z = fmaf(w[e], b0.z, s0.z); s0.w = fmaf(w[e], b0.w, s0.w);
        s1.x = fmaf(w[e], b1.x, s1.x); s1.y = fmaf(w[e], b1.y, s1.y);
        s1.z = fmaf(w[e], b1.z, s1.z); s1.w = fmaf(w[e], b1.w, s1.w);
    }
    *(float4*)(out + off)     = s0;
    *(float4*)(out + off + 4) = s1;
}

extern "C" void kernel_launch(void* const* d_in, const int* in_sizes, int n_in,
                              void* d_out, int out_size)
{
    const float* x    = (const float*)d_in[0];   // [512, 1024]
    const float* ew   = (const float*)d_in[1];   // [512, 8]
    const float* W    = (const float*)d_in[2];   // [8, 1024, 1024]
    const float* bias = (const float*)d_in[3];   // [8, 1024]
    float* out = (float*)d_out;

    prep_kernel<<<W_BLOCKS + X_BLOCKS, 256>>>(x, ew, W);

    cudaFuncSetAttribute(moe_gemm_kernel,
                         cudaFuncAttributeMaxDynamicSharedMemorySize, SMEM_TOTAL);
    dim3 grid(OUT_DIM / NT, B_DIM / MT, ZSPLIT);   // (8, 4, 4) = 128 CTAs
    moe_gemm_kernel<<<grid, THREADS, SMEM_TOTAL>>>();

    combine_kernel<<<B_DIM * OUT_DIM / 8 / 256, 256>>>(ew, bias, out);
}

// round 7
// speedup vs baseline: 7.1925x; 1.1202x over previous
#include <cuda_runtime.h>
#include <cuda_fp16.h>
#include <cstdint>

#define B_DIM   512
#define E_DIM   8
#define IN_DIM  1024
#define OUT_DIM 1024

#define MT 128
#define NT 128
#define KC 64                        // K chunk (fp16) = 128B row
#define ZSPLIT 8
#define NCHUNK (IN_DIM / KC)         // 16 (one expert per CTA)
#define THREADS 256

#define TILE_BYTES (128 * 128)       // 16KB per operand tile
#define BUFSZ (2 * TILE_BYTES)       // A + B
#define SMEM_TOTAL (2 * BUFSZ)       // 64KB double-buffered

// scratch (no cudaMalloc allowed)
__device__ __half g_xs[E_DIM * B_DIM * IN_DIM];      // pre-blended A planes, 8MB
__device__ __half g_wh[E_DIM * OUT_DIM * IN_DIM];    // fp16 W, 16.8MB
__device__ float  g_partial[ZSPLIT * B_DIM * OUT_DIM];

// ---------- helpers ----------
__device__ __forceinline__ uint32_t smem_u32(const void* p) {
    uint32_t a;
    asm("{ .reg .u64 t; cvta.to.shared.u64 t, %1; cvt.u32.u64 %0, t; }" : "=r"(a) : "l"(p));
    return a;
}
__device__ __forceinline__ void cp16(uint32_t dst, const void* src) {
    asm volatile("cp.async.cg.shared.global [%0], [%1], 16;" :: "r"(dst), "l"(src));
}
__device__ __forceinline__ void ldsm_x4(uint32_t* r, uint32_t addr) {
    asm volatile("ldmatrix.sync.aligned.m8n8.x4.shared.b16 {%0,%1,%2,%3}, [%4];"
                 : "=r"(r[0]), "=r"(r[1]), "=r"(r[2]), "=r"(r[3]) : "r"(addr));
}
__device__ __forceinline__ void mma_fp16(float* c, const uint32_t* a,
                                         uint32_t b0, uint32_t b1) {
    asm volatile(
        "mma.sync.aligned.m16n8k16.row.col.f32.f16.f16.f32 "
        "{%0,%1,%2,%3}, {%4,%5,%6,%7}, {%8,%9}, {%0,%1,%2,%3};"
        : "+f"(c[0]), "+f"(c[1]), "+f"(c[2]), "+f"(c[3])
        : "r"(a[0]), "r"(a[1]), "r"(a[2]), "r"(a[3]), "r"(b0), "r"(b1));
}
__device__ __forceinline__ uint32_t sw_off(int r, int kb) {
    return (uint32_t)(r * 128 + ((kb ^ (r & 7)) << 4));
}
__device__ __forceinline__ uint2 cvt8(float4 a, float4 b) {
    __half2 h0 = __floats2half2_rn(a.x, a.y);
    __half2 h1 = __floats2half2_rn(a.z, a.w);
    (void)b;
    return make_uint2(*(uint32_t*)&h0, *(uint32_t*)&h1);
}

// ---------- prep: W->fp16 and x->pre-blended fp16 planes (8 elems/thread) ----------
#define W_BLOCKS (E_DIM * OUT_DIM * IN_DIM / 8 / 256)   // 4096
#define X_BLOCKS (B_DIM * IN_DIM / 8 / 256)             // 256
__global__ __launch_bounds__(256)
void prep_kernel(const float* __restrict__ x,
                 const float* __restrict__ ew,
                 const float* __restrict__ W)
{
    if (blockIdx.x < W_BLOCKS) {
        const size_t idx = ((size_t)blockIdx.x * 256 + threadIdx.x) * 8;
        const float4 v0 = __ldg((const float4*)(W + idx));
        const float4 v1 = __ldg((const float4*)(W + idx + 4));
        __half2 a = __floats2half2_rn(v0.x, v0.y);
        __half2 b = __floats2half2_rn(v0.z, v0.w);
        __half2 c = __floats2half2_rn(v1.x, v1.y);
        __half2 d = __floats2half2_rn(v1.z, v1.w);
        *(uint4*)(g_wh + idx) = make_uint4(*(uint32_t*)&a, *(uint32_t*)&b,
                                           *(uint32_t*)&c, *(uint32_t*)&d);
    } else {
        const int idx = ((blockIdx.x - W_BLOCKS) * 256 + threadIdx.x) * 8;
        const int b = idx >> 10;
        const float4 v0 = __ldg((const float4*)(x + idx));
        const float4 v1 = __ldg((const float4*)(x + idx + 4));
        #pragma unroll
        for (int e = 0; e < E_DIM; ++e) {
            const float s = __ldg(&ew[b * E_DIM + e]);
            __half2 a = __floats2half2_rn(v0.x * s, v0.y * s);
            __half2 c = __floats2half2_rn(v0.z * s, v0.w * s);
            __half2 d = __floats2half2_rn(v1.x * s, v1.y * s);
            __half2 f = __floats2half2_rn(v1.z * s, v1.w * s);
            *(uint4*)(g_xs + (size_t)e * (B_DIM * IN_DIM) + idx) =
                make_uint4(*(uint32_t*)&a, *(uint32_t*)&c,
                           *(uint32_t*)&d, *(uint32_t*)&f);
        }
    }
}

// ---------- GEMM: partial_e = (ew_e*x) @ W_e^T ----------
__global__ __launch_bounds__(THREADS, 2)
void moe_gemm_kernel()
{
    extern __shared__ __align__(16) uint8_t smem[];
    const uint32_t sbase = smem_u32(smem);

    const int tid  = threadIdx.x;
    const int lane = tid & 31;
    const int wid  = tid >> 5;
    const int bn = blockIdx.x * NT;
    const int bm = blockIdx.y * MT;
    const int e  = blockIdx.z;

    const int wm = wid >> 2;        // 0..1 -> 64 rows
    const int wn = wid & 3;         // 0..3 -> 32 cols

    const __half* ap = g_xs + (size_t)e * (B_DIM * IN_DIM);
    const __half* bp = g_wh + (size_t)e * (OUT_DIM * IN_DIM);

    float acc[16][4];
    #pragma unroll
    for (int i = 0; i < 16; ++i)
        #pragma unroll
        for (int j = 0; j < 4; ++j) acc[i][j] = 0.0f;

    auto issue = [&](int c, int buf) {
        const int k0 = c * KC;
        const uint32_t base = sbase + buf * BUFSZ;
        #pragma unroll
        for (int j = 0; j < 4; ++j) {
            const int cid = tid + j * 256;     // 0..1023
            const int row = cid >> 3;
            const int kb  = cid & 7;
            const uint32_t d = sw_off(row, kb);
            const int goff = k0 + kb * 8;
            cp16(base + d,              ap + (size_t)(bm + row) * IN_DIM + goff);
            cp16(base + TILE_BYTES + d, bp + (size_t)(bn + row) * IN_DIM + goff);
        }
        asm volatile("cp.async.commit_group;" ::: "memory");
    };

    issue(0, 0);

    for (int c = 0; c < NCHUNK; ++c) {
        const int buf = c & 1;
        if (c + 1 < NCHUNK) {
            issue(c + 1, buf ^ 1);
            asm volatile("cp.async.wait_group 1;" ::: "memory");
        } else {
            asm volatile("cp.async.wait_group 0;" ::: "memory");
        }
        __syncthreads();

        const uint32_t uA = sbase + buf * BUFSZ;
        const uint32_t uB = uA + TILE_BYTES;

        #pragma unroll
        for (int ks = 0; ks < 4; ++ks) {
            uint32_t ah[4][4];
            const int ar  = lane & 15;
            const int akb = ks * 2 + (lane >> 4);
            #pragma unroll
            for (int mt = 0; mt < 4; ++mt) {
                const int r = wm * 64 + mt * 16 + ar;
                ldsm_x4(ah[mt], uA + sw_off(r, akb));
            }
            uint32_t bh[2][4];
            #pragma unroll
            for (int p = 0; p < 2; ++p) {
                const int r  = wn * 32 + p * 16 + (lane & 7) + ((lane >> 4) & 1) * 8;
                const int kb = ks * 2 + ((lane >> 3) & 1);
                ldsm_x4(bh[p], uB + sw_off(r, kb));
            }
            #pragma unroll
            for (int mt = 0; mt < 4; ++mt)
                #pragma unroll
                for (int p = 0; p < 2; ++p)
                    #pragma unroll
                    for (int sub = 0; sub < 2; ++sub)
                        mma_fp16(acc[mt * 4 + p * 2 + sub], ah[mt],
                                 bh[p][sub * 2], bh[p][sub * 2 + 1]);
        }
        __syncthreads();
    }

    // epilogue -> partial plane e
    const int tr = lane >> 2;
    const int tc = (lane & 3) * 2;
    #pragma unroll
    for (int mt = 0; mt < 4; ++mt) {
        const int row = bm + wm * 64 + mt * 16 + tr;
        float* base = g_partial + ((size_t)e * B_DIM + row) * OUT_DIM + bn + wn * 32;
        #pragma unroll
        for (int nt = 0; nt < 4; ++nt) {
            const float* a4 = acc[mt * 4 + nt];
            *(float2*)(base + nt * 8 + tc)                       = make_float2(a4[0], a4[1]);
            *(float2*)(base + 8 * (size_t)OUT_DIM + nt * 8 + tc) = make_float2(a4[2], a4[3]);
        }
    }
}

// ---------- combine: sum 8 partial planes + blended bias ----------
__global__ __launch_bounds__(256)
void combine_kernel(const float* __restrict__ ew,
                    const float* __restrict__ bias,
                    float* __restrict__ out)
{
    const int idx = (blockIdx.x * 256 + threadIdx.x) * 8;   // 8 floats/thread
    const int b   = idx >> 10;
    const int o   = idx & 1023;
    const size_t off = (size_t)b * OUT_DIM + o;
    const size_t plane = (size_t)B_DIM * OUT_DIM;

    float w[E_DIM];
    #pragma unroll
    for (int e = 0; e < E_DIM; ++e) w[e] = __ldg(&ew[b * E_DIM + e]);

    float4 s0 = make_float4(0.f, 0.f, 0.f, 0.f);
    float4 s1 = make_float4(0.f, 0.f, 0.f, 0.f);
    #pragma unroll
    for (int zz = 0; zz < ZSPLIT; ++zz) {
        const float4 p0 = *(const float4*)&g_partial[zz * plane + off];
        const float4 p1 = *(const float4*)&g_partial[zz * plane + off + 4];
        s0.x += p0.x; s0.y += p0.y; s0.z += p0.z; s0.w += p0.w;
        s1.x += p1.x; s1.y += p1.y; s1.z += p1.z; s1.w += p1.w;
    }
    #pragma unroll
    for (int e = 0; e < E_DIM; ++e) {
        const float4 b0 = *(const float4*)&bias[e * OUT_DIM + o];
        const float4 b1 = *(const float4*)&bias[e * OUT_DIM + o + 4];
        s0.x = fmaf(w[e], b0.x, s0.x); s0.y = fmaf(w[e], b0.y, s0.y);
        s0.z = fmaf(w[e], b0.z, s0.z); s0.w = fmaf(w[e], b0.w, s0.w);
        s1.x = fmaf(w[e], b1.x, s1.x); s1.y = fmaf(w[e], b1.y, s1.y);
        s1.z = fmaf(w[e], b1.z, s1.z); s1.w = fmaf(w[e], b1.w, s1.w);
    }
    *(float4*)(out + off)     = s0;
    *(float4*)(out + off + 4) = s1;
}

extern "C" void kernel_launch(void* const* d_in, const int* in_sizes, int n_in,
                              void* d_out, int out_size)
{
    const float* x    = (const float*)d_in[0];   // [512, 1024]
    const float* ew   = (const float*)d_in[1];   // [512, 8]
    const float* W    = (const float*)d_in[2];   // [8, 1024, 1024]
    const float* bias = (const float*)d_in[3];   // [8, 1024]
    float* out = (float*)d_out;

    prep_kernel<<<W_BLOCKS + X_BLOCKS, 256>>>(x, ew, W);

    cudaFuncSetAttribute(moe_gemm_kernel,
                         cudaFuncAttributeMaxDynamicSharedMemorySize, SMEM_TOTAL);
    dim3 grid(OUT_DIM / NT, B_DIM / MT, ZSPLIT);   // (8, 4, 8) = 256 CTAs
    moe_gemm_kernel<<<grid, THREADS, SMEM_TOTAL>>>();

    combine_kernel<<<B_DIM * OUT_DIM / 8 / 256, 256>>>(ew, bias, out);
}